// round 11
// baseline (speedup 1.0000x reference)
#include <cuda_runtime.h>
#include <math.h>
#include <stdint.h>

#define Bdim 256
#define Jdim 64
#define Ddim 512

// ---- scratch (allocation-free rule: __device__ globals) ----
__device__ float g_Q[Bdim * Ddim];          // inputs @ W
__device__ float g_P[Jdim * Ddim];          // keys @ V + U_bias
__device__ float g_R[Bdim * Jdim * 4];      // per-(row, colblk) partial sum-of-squares
// U pre-split, transposed, k-interleaved (R9 layout):
// g_U2T[(col*64 + s)*4 + p] = { hi(U[8s+p][col]), lo(U[8s+p][col]),
//                               hi(U[8s+p+4][col]), lo(U[8s+p+4][col]) }
__device__ uint4 g_U2T[Ddim * 64 * 4];
// state pre-split: g_A2[row*512 + k] = { tf32hi(state), tf32lo(state) }
__device__ uint2 g_A2[(size_t)Bdim * Jdim * Ddim];

// ---------------- cp.async helpers ----------------
__device__ __forceinline__ void cp_async16(void* smem_dst, const void* gmem_src) {
    unsigned s = (unsigned)__cvta_generic_to_shared(smem_dst);
    asm volatile("cp.async.cg.shared.global [%0], [%1], 16;\n" :: "r"(s), "l"(gmem_src));
}
__device__ __forceinline__ void cp_commit() { asm volatile("cp.async.commit_group;\n"); }
__device__ __forceinline__ void cp_wait1()  { asm volatile("cp.async.wait_group 1;\n"); }
__device__ __forceinline__ void cp_wait0()  { asm volatile("cp.async.wait_group 0;\n"); }

// ---------------- tf32 helpers ----------------
__device__ __forceinline__ unsigned f2tf32(float x) {
    unsigned r;
    asm("cvt.rna.tf32.f32 %0, %1;" : "=r"(r) : "f"(x));
    return r;
}
__device__ __forceinline__ void split_tf32(float x, unsigned& hi, unsigned& lo) {
    hi = f2tf32(x);
    lo = f2tf32(x - __uint_as_float(hi));
}
// D += A(16x8,row) * B(8x8,col)   (tf32 in, fp32 acc)
__device__ __forceinline__ void mma_tf32(float d[4], const unsigned a[4], unsigned b0, unsigned b1) {
    asm volatile("mma.sync.aligned.m16n8k8.row.col.f32.tf32.tf32.f32 "
        "{%0,%1,%2,%3}, {%4,%5,%6,%7}, {%8,%9}, {%0,%1,%2,%3};"
        : "+f"(d[0]), "+f"(d[1]), "+f"(d[2]), "+f"(d[3])
        : "r"(a[0]), "r"(a[1]), "r"(a[2]), "r"(a[3]), "r"(b0), "r"(b1));
}

// ---------------- precompute ----------------
__device__ __forceinline__ void sgemm_tile_body(
    const float* __restrict__ A, const float* __restrict__ Bm,
    const float* __restrict__ bias, float* __restrict__ C,
    int m0, int n0, int N, int K,
    float (*As)[64], float (*Bs)[64])
{
    int tid = threadIdx.x;
    int ty = tid >> 4, tx = tid & 15;
    float acc[4][4];
#pragma unroll
    for (int i = 0; i < 4; i++)
#pragma unroll
        for (int j = 0; j < 4; j++) acc[i][j] = 0.f;
    for (int k0 = 0; k0 < K; k0 += 16) {
        {
            int m = tid >> 2, kk = (tid & 3) * 4;
            float4 v = *reinterpret_cast<const float4*>(&A[(size_t)(m0 + m) * K + k0 + kk]);
            As[kk + 0][m] = v.x; As[kk + 1][m] = v.y;
            As[kk + 2][m] = v.z; As[kk + 3][m] = v.w;
        }
        {
            int kk = tid >> 4, c4 = (tid & 15) * 4;
            *reinterpret_cast<float4*>(&Bs[kk][c4]) =
                *reinterpret_cast<const float4*>(&Bm[(size_t)(k0 + kk) * N + n0 + c4]);
        }
        __syncthreads();
#pragma unroll
        for (int kk = 0; kk < 16; kk++) {
            float4 a4 = *reinterpret_cast<const float4*>(&As[kk][ty * 4]);
            float4 b4 = *reinterpret_cast<const float4*>(&Bs[kk][tx * 4]);
            float a[4] = {a4.x, a4.y, a4.z, a4.w};
            float b[4] = {b4.x, b4.y, b4.z, b4.w};
#pragma unroll
            for (int i = 0; i < 4; i++)
#pragma unroll
                for (int j = 0; j < 4; j++) acc[i][j] += a[i] * b[j];
        }
        __syncthreads();
    }
    float bx = 0.f, by = 0.f, bz = 0.f, bw = 0.f;
    if (bias) {
        bx = bias[n0 + tx * 4 + 0]; by = bias[n0 + tx * 4 + 1];
        bz = bias[n0 + tx * 4 + 2]; bw = bias[n0 + tx * 4 + 3];
    }
#pragma unroll
    for (int i = 0; i < 4; i++) {
        float4 o;
        o.x = acc[i][0] + bx; o.y = acc[i][1] + by;
        o.z = acc[i][2] + bz; o.w = acc[i][3] + bw;
        *reinterpret_cast<float4*>(&C[(size_t)(m0 + ty * 4 + i) * N + n0 + tx * 4]) = o;
    }
}

// blocks: [0,32) Q ; [32,40) P ; [40,168) U2T ; [168,1192) A2
__global__ __launch_bounds__(256) void precompute_kernel(
    const float* __restrict__ inputs, const float* __restrict__ keys,
    const float* __restrict__ state,
    const float* __restrict__ V, const float* __restrict__ W,
    const float* __restrict__ U, const float* __restrict__ Ubias)
{
    __shared__ float As[16][64];
    __shared__ float Bs[16][64];
    int bx = blockIdx.x, tid = threadIdx.x;
    if (bx < 32) {
        sgemm_tile_body(inputs, W, nullptr, g_Q,
                        (bx >> 3) * 64, (bx & 7) * 64, Ddim, Ddim, As, Bs);
    } else if (bx < 40) {
        sgemm_tile_body(keys, V, Ubias, g_P, 0, (bx - 32) * 64, Ddim, Ddim, As, Bs);
    } else if (bx < 168) {
        // U -> g_U2T (R9 layout)
        int id = (bx - 40) * 256 + tid;          // 0..32767
        int col = id >> 6;
        int s   = id & 63;
#pragma unroll
        for (int p = 0; p < 4; p++) {
            float a = U[(size_t)(8 * s + p) * Ddim + col];
            float b = U[(size_t)(8 * s + p + 4) * Ddim + col];
            uint4 o;
            split_tf32(a, o.x, o.y);
            split_tf32(b, o.z, o.w);
            g_U2T[((size_t)col * 64 + s) * 4 + p] = o;
        }
    } else {
        // state -> g_A2 : 1024 blocks, each thread 8 float4 (32 elems)
        size_t id = (size_t)(bx - 168) * 256 + tid;   // 0..262143
        const float4* s4 = reinterpret_cast<const float4*>(state);
        uint4* A4 = reinterpret_cast<uint4*>(g_A2);
#pragma unroll
        for (int q = 0; q < 8; q++) {
            size_t i4 = id * 8 + q;
            float4 u = s4[i4];
            uint4 o0, o1;
            split_tf32(u.x, o0.x, o0.y);
            split_tf32(u.y, o0.z, o0.w);
            split_tf32(u.z, o1.x, o1.y);
            split_tf32(u.w, o1.z, o1.w);
            A4[i4 * 2 + 0] = o0;
            A4[i4 * 2 + 1] = o1;
        }
    }
}

// ---------------- fused main kernel ----------------
// Grid 2048: rowblk = bx>>2 (32 rows, one (b, j-half)), colblk = bx&3 (128 cols).
// 256 threads = 8 warps: wr = w>>2 (row half of 16), wc = w&3 (32-col slice).
// Warp tile 16x32, 16 fp32 accums -> low regs -> 3 CTAs/SM (6 warps/SMSP).
// Writes raw v to out and partial sum-of-squares to g_R; finalize kernel applies norm.
__global__ __launch_bounds__(256, 3) void fused_kernel(
    const float* __restrict__ inputs,
    const float* __restrict__ state,
    const float* __restrict__ keys,
    float* __restrict__ out)
{
    extern __shared__ char smraw[];
    uint4* Bbuf  = reinterpret_cast<uint4*>(smraw);            // 8 warps x [2][32][4] uint4 = 32KB
    float* gate  = reinterpret_cast<float*>(smraw + 32768);    // [32]
    float* red   = reinterpret_cast<float*>(smraw + 32896);    // [4][32]

    int tid    = threadIdx.x;
    int bx     = blockIdx.x;
    int rowblk = bx >> 2;
    int colblk = bx & 3;
    int row0   = rowblk * 32;
    int b      = rowblk >> 1;
    int j0     = (rowblk & 1) * 32;

    int lane = tid & 31;
    int w    = tid >> 5;
    int wr   = w >> 2;               // 0/1: rows wr*16 .. wr*16+15
    int wc   = w & 3;                // 32-col slice within the CTA's 128
    int gid  = lane >> 2;            // 0..7
    int tig  = lane & 3;             // 0..3
    int cb   = colblk * 128 + wc * 32;   // warp's absolute column base

    uint4* mybuf = Bbuf + w * 256;   // [2][32][4] uint4 (4KB)
    const uint4* usrc = g_U2T + (size_t)cb * 256;  // col-major: col*256 + s*4 + p

    // per-warp prefetch of B slabs 0 and 1 (each 32 cols x 4 p = 128 uint4 = 2KB)
#pragma unroll
    for (int st = 0; st < 2; st++) {
#pragma unroll
        for (int q = 0; q < 4; q++) {
            int idx = lane + 32 * q;             // 0..127
            int col = idx >> 2, p = idx & 3;
            cp_async16(mybuf + st * 128 + idx, usrc + (size_t)col * 256 + st * 4 + p);
        }
        cp_commit();
    }

    // Gates: warp w -> rows 4w..4w+3 ; z = inputs[b].(s_row + key_j)
    {
        const float* ir = inputs + (size_t)b * Ddim;
#pragma unroll
        for (int i = 0; i < 4; i++) {
            int r = w * 4 + i;
            const float* sr = state + (size_t)(row0 + r) * Ddim;
            const float* kr = keys + (size_t)(j0 + r) * Ddim;
            float z = 0.f;
            for (int k = lane; k < Ddim; k += 32)
                z += ir[k] * (sr[k] + kr[k]);
#pragma unroll
            for (int o = 16; o; o >>= 1) z += __shfl_xor_sync(0xffffffffu, z, o);
            if (lane == 0) gate[r] = 1.f / (1.f + expf(-z));
        }
    }

    // -------- barrier-free mainloop: 64 k-slabs, split-3 tf32 --------
    float acc[4][4];                 // [nf][frag]
#pragma unroll
    for (int nf = 0; nf < 4; nf++)
#pragma unroll
        for (int c = 0; c < 4; c++) acc[nf][c] = 0.f;

    const uint2* Ar0 = g_A2 + (size_t)(row0 + wr * 16 + gid) * Ddim;
    const uint2* Ar8 = Ar0 + (size_t)8 * Ddim;

#pragma unroll 1
    for (int s = 0; s < 64; s++) {
        if (s < 62) cp_wait1(); else cp_wait0();
        __syncwarp();
        int k0 = s * 8;

        // A fragments (pre-split, no CVTs): 4 x LDG.64
        uint2 a0 = Ar0[k0 + tig];
        uint2 a1 = Ar8[k0 + tig];
        uint2 a2 = Ar0[k0 + tig + 4];
        uint2 a3 = Ar8[k0 + tig + 4];
        unsigned ah[4] = {a0.x, a1.x, a2.x, a3.x};
        unsigned al[4] = {a0.y, a1.y, a2.y, a3.y};

        const uint4* Bs = mybuf + (s & 1) * 128;
#pragma unroll
        for (int pr = 0; pr < 2; pr++) {
            int nf0 = pr * 2;
            uint4 b0 = Bs[((nf0 + 0) * 8 + gid) * 4 + tig];
            uint4 b1 = Bs[((nf0 + 1) * 8 + gid) * 4 + tig];
            // hh
            mma_tf32(acc[nf0 + 0], ah, b0.x, b0.z);
            mma_tf32(acc[nf0 + 1], ah, b1.x, b1.z);
            // lh
            mma_tf32(acc[nf0 + 0], al, b0.x, b0.z);
            mma_tf32(acc[nf0 + 1], al, b1.x, b1.z);
            // hl
            mma_tf32(acc[nf0 + 0], ah, b0.y, b0.w);
            mma_tf32(acc[nf0 + 1], ah, b1.y, b1.w);
        }

        if (s + 2 < 64) {
            uint4* Ud = mybuf + (s & 1) * 128;
#pragma unroll
            for (int q = 0; q < 4; q++) {
                int idx = lane + 32 * q;
                int col = idx >> 2, p = idx & 3;
                cp_async16(Ud + idx, usrc + (size_t)col * 256 + (s + 2) * 4 + p);
            }
            cp_commit();
        }
    }

    __syncthreads();   // gates visible

    // -------- epilogue: v = s + g*relu(acc + Q + P); write raw v + partial norms --------
    const float* Qb = g_Q + (size_t)b * Ddim;
    float part[2];
#pragma unroll
    for (int h = 0; h < 2; h++) {
        int r = wr * 16 + h * 8 + gid;           // 0..31
        int grow = row0 + r;
        float g = gate[r];
        const float* Pr = g_P + (size_t)(j0 + r) * Ddim;
        const float* Sr = state + (size_t)grow * Ddim;
        float* orow = out + (size_t)grow * Ddim;
        float psum = 0.f;
#pragma unroll
        for (int nf = 0; nf < 4; nf++) {
            int c0 = cb + nf * 8 + tig * 2;
            float2 p2 = *reinterpret_cast<const float2*>(Pr + c0);
            float2 q2 = *reinterpret_cast<const float2*>(Qb + c0);
            float2 s2 = *reinterpret_cast<const float2*>(Sr + c0);
            float v0 = s2.x + g * fmaxf(acc[nf][h * 2 + 0] + q2.x + p2.x, 0.f);
            float v1 = s2.y + g * fmaxf(acc[nf][h * 2 + 1] + q2.y + p2.y, 0.f);
            float2 o; o.x = v0; o.y = v1;
            *reinterpret_cast<float2*>(orow + c0) = o;
            psum += v0 * v0 + v1 * v1;
        }
        part[h] = psum;
    }
#pragma unroll
    for (int h = 0; h < 2; h++) {
        part[h] += __shfl_xor_sync(0xffffffffu, part[h], 1);
        part[h] += __shfl_xor_sync(0xffffffffu, part[h], 2);
    }
    if (tig == 0) {
#pragma unroll
        for (int h = 0; h < 2; h++)
            red[wc * 32 + wr * 16 + h * 8 + gid] = part[h];
    }
    __syncthreads();
    if (tid < 32) {
        float sum = red[tid] + red[32 + tid] + red[64 + tid] + red[96 + tid];
        g_R[(size_t)(row0 + tid) * 4 + colblk] = sum;
    }
}

// ---------------- finalize: out = (v > 0) ? ||v_row|| : v ----------------
__global__ __launch_bounds__(256) void finalize_kernel(float* __restrict__ out)
{
    int tid = threadIdx.x;
    int row = blockIdx.x * 32 + (tid >> 3);
    int seg = tid & 7;
    const float* Rr = g_R + (size_t)row * 4;
    float n = fmaxf(sqrtf(Rr[0] + Rr[1] + Rr[2] + Rr[3]), 1e-12f);
    float4* o4 = reinterpret_cast<float4*>(out + (size_t)row * Ddim + seg * 64);
#pragma unroll
    for (int q = 0; q < 16; q++) {
        float4 v = o4[q];
        v.x = v.x > 0.f ? n : v.x;
        v.y = v.y > 0.f ? n : v.y;
        v.z = v.z > 0.f ? n : v.z;
        v.w = v.w > 0.f ? n : v.w;
        o4[q] = v;
    }
}

extern "C" void kernel_launch(void* const* d_in, const int* in_sizes, int n_in,
                              void* d_out, int out_size)
{
    const float* inputs = (const float*)d_in[0];
    const float* state  = (const float*)d_in[1];
    const float* keys   = (const float*)d_in[2];
    const float* U      = (const float*)d_in[3];
    const float* V      = (const float*)d_in[4];
    const float* W      = (const float*)d_in[5];
    const float* Ubias  = (const float*)d_in[6];
    float* out = (float*)d_out;
    (void)in_sizes; (void)n_in; (void)out_size;

    // Q(32) + P(8) + U2T(128) + A2(1024) = 1192 blocks
    precompute_kernel<<<1192, 256>>>(inputs, keys, state, V, W, U, Ubias);

    size_t smem = 32768 + (32 + 128) * sizeof(float);
    cudaFuncSetAttribute(fused_kernel, cudaFuncAttributeMaxDynamicSharedMemorySize, (int)smem);
    fused_kernel<<<2048, 256, smem>>>(inputs, state, keys, out);

    finalize_kernel<<<Bdim * Jdim / 32, 256>>>(out);
}

// round 12
// speedup vs baseline: 2.2037x; 2.2037x over previous
#include <cuda_runtime.h>
#include <cuda_fp16.h>
#include <math.h>
#include <stdint.h>

#define Bdim 256
#define Jdim 64
#define Ddim 512

// ---- scratch (allocation-free rule: __device__ globals) ----
__device__ float g_Q[Bdim * Ddim];     // inputs @ W
__device__ float g_P[Jdim * Ddim];     // keys @ V + U_bias
// U pre-split fp16, transposed, k16-interleaved:
// g_UH[(col*32 + s)*4 + tig] = { hi2(k=16s+2tig..+1), hi2(k=16s+2tig+8..+9),
//                                lo2(k=16s+2tig..+1), lo2(k=16s+2tig+8..+9) }
__device__ uint4 g_UH[Ddim * 32 * 4];
// state pre-split fp16: g_A2h[row*256 + kp] = { hi2(k=2kp,2kp+1), lo2(k=2kp,2kp+1) }
__device__ uint2 g_A2h[(size_t)Bdim * Jdim * 256];

// ---------------- cp.async helpers ----------------
__device__ __forceinline__ void cp_async16(void* smem_dst, const void* gmem_src) {
    unsigned s = (unsigned)__cvta_generic_to_shared(smem_dst);
    asm volatile("cp.async.cg.shared.global [%0], [%1], 16;\n" :: "r"(s), "l"(gmem_src));
}
__device__ __forceinline__ void cp_commit() { asm volatile("cp.async.commit_group;\n"); }
__device__ __forceinline__ void cp_wait1()  { asm volatile("cp.async.wait_group 1;\n"); }
__device__ __forceinline__ void cp_wait0()  { asm volatile("cp.async.wait_group 0;\n"); }

// ---------------- fp16 split helpers ----------------
__device__ __forceinline__ void split_h(float x, unsigned short& hi, unsigned short& lo) {
    __half h = __float2half_rn(x);
    hi = __half_as_ushort(h);
    lo = __half_as_ushort(__float2half_rn(x - __half2float(h)));
}
__device__ __forceinline__ unsigned pack2(unsigned short a, unsigned short b) {
    return (unsigned)a | ((unsigned)b << 16);
}
// D += A(16x16,row) * B(16x8,col)   (fp16 in, fp32 acc)
__device__ __forceinline__ void mma_f16(float d[4], const unsigned a[4], unsigned b0, unsigned b1) {
    asm volatile("mma.sync.aligned.m16n8k16.row.col.f32.f16.f16.f32 "
        "{%0,%1,%2,%3}, {%4,%5,%6,%7}, {%8,%9}, {%0,%1,%2,%3};"
        : "+f"(d[0]), "+f"(d[1]), "+f"(d[2]), "+f"(d[3])
        : "r"(a[0]), "r"(a[1]), "r"(a[2]), "r"(a[3]), "r"(b0), "r"(b1));
}

// ---------------- precompute ----------------
__device__ __forceinline__ void sgemm_tile_body(
    const float* __restrict__ A, const float* __restrict__ Bm,
    const float* __restrict__ bias, float* __restrict__ C,
    int m0, int n0, int N, int K,
    float (*As)[64], float (*Bs)[64])
{
    int tid = threadIdx.x;
    int ty = tid >> 4, tx = tid & 15;
    float acc[4][4];
#pragma unroll
    for (int i = 0; i < 4; i++)
#pragma unroll
        for (int j = 0; j < 4; j++) acc[i][j] = 0.f;
    for (int k0 = 0; k0 < K; k0 += 16) {
        {
            int m = tid >> 2, kk = (tid & 3) * 4;
            float4 v = *reinterpret_cast<const float4*>(&A[(size_t)(m0 + m) * K + k0 + kk]);
            As[kk + 0][m] = v.x; As[kk + 1][m] = v.y;
            As[kk + 2][m] = v.z; As[kk + 3][m] = v.w;
        }
        {
            int kk = tid >> 4, c4 = (tid & 15) * 4;
            *reinterpret_cast<float4*>(&Bs[kk][c4]) =
                *reinterpret_cast<const float4*>(&Bm[(size_t)(k0 + kk) * N + n0 + c4]);
        }
        __syncthreads();
#pragma unroll
        for (int kk = 0; kk < 16; kk++) {
            float4 a4 = *reinterpret_cast<const float4*>(&As[kk][ty * 4]);
            float4 b4 = *reinterpret_cast<const float4*>(&Bs[kk][tx * 4]);
            float a[4] = {a4.x, a4.y, a4.z, a4.w};
            float b[4] = {b4.x, b4.y, b4.z, b4.w};
#pragma unroll
            for (int i = 0; i < 4; i++)
#pragma unroll
                for (int j = 0; j < 4; j++) acc[i][j] += a[i] * b[j];
        }
        __syncthreads();
    }
    float bx = 0.f, by = 0.f, bz = 0.f, bw = 0.f;
    if (bias) {
        bx = bias[n0 + tx * 4 + 0]; by = bias[n0 + tx * 4 + 1];
        bz = bias[n0 + tx * 4 + 2]; bw = bias[n0 + tx * 4 + 3];
    }
#pragma unroll
    for (int i = 0; i < 4; i++) {
        float4 o;
        o.x = acc[i][0] + bx; o.y = acc[i][1] + by;
        o.z = acc[i][2] + bz; o.w = acc[i][3] + bw;
        *reinterpret_cast<float4*>(&C[(size_t)(m0 + ty * 4 + i) * N + n0 + tx * 4]) = o;
    }
}

// blocks: [0,32) Q ; [32,40) P ; [40,104) UH ; [104,2152) A2h
__global__ __launch_bounds__(256) void precompute_kernel(
    const float* __restrict__ inputs, const float* __restrict__ keys,
    const float* __restrict__ state,
    const float* __restrict__ V, const float* __restrict__ W,
    const float* __restrict__ U, const float* __restrict__ Ubias)
{
    __shared__ float As[16][64];
    __shared__ float Bs[16][64];
    int bx = blockIdx.x, tid = threadIdx.x;
    if (bx < 32) {
        sgemm_tile_body(inputs, W, nullptr, g_Q,
                        (bx >> 3) * 64, (bx & 7) * 64, Ddim, Ddim, As, Bs);
    } else if (bx < 40) {
        sgemm_tile_body(keys, V, Ubias, g_P, 0, (bx - 32) * 64, Ddim, Ddim, As, Bs);
    } else if (bx < 104) {
        // U -> g_UH : 64 blocks x 256 threads = 16384 (col, s) tasks
        int id = (bx - 40) * 256 + tid;
        int col = id >> 5;
        int s   = id & 31;
#pragma unroll
        for (int tg = 0; tg < 4; tg++) {
            int k = 16 * s + 2 * tg;
            unsigned short h0, l0, h1, l1, h2, l2, h3, l3;
            split_h(U[(size_t)(k + 0) * Ddim + col], h0, l0);
            split_h(U[(size_t)(k + 1) * Ddim + col], h1, l1);
            split_h(U[(size_t)(k + 8) * Ddim + col], h2, l2);
            split_h(U[(size_t)(k + 9) * Ddim + col], h3, l3);
            uint4 o;
            o.x = pack2(h0, h1);   // hi2 @ k, k+1
            o.y = pack2(h2, h3);   // hi2 @ k+8, k+9
            o.z = pack2(l0, l1);   // lo2 @ k, k+1
            o.w = pack2(l2, l3);   // lo2 @ k+8, k+9
            g_UH[((size_t)col * 32 + s) * 4 + tg] = o;
        }
    } else {
        // state -> g_A2h : 2048 blocks, each thread 4 float4 (16 elems -> 8 uint2)
        size_t id = (size_t)(bx - 104) * 256 + tid;     // 0..524287
        const float4* s4 = reinterpret_cast<const float4*>(state);
        uint4* A4 = reinterpret_cast<uint4*>(g_A2h);
#pragma unroll
        for (int q = 0; q < 4; q++) {
            size_t i4 = id * 4 + q;
            float4 u = s4[i4];
            unsigned short h0, l0, h1, l1, h2, l2, h3, l3;
            split_h(u.x, h0, l0);
            split_h(u.y, h1, l1);
            split_h(u.z, h2, l2);
            split_h(u.w, h3, l3);
            uint4 o;
            o.x = pack2(h0, h1);   // hi2 kpair 2j
            o.y = pack2(l0, l1);   // lo2 kpair 2j
            o.z = pack2(h2, h3);   // hi2 kpair 2j+1
            o.w = pack2(l2, l3);   // lo2 kpair 2j+1
            A4[i4] = o;
        }
    }
}

// ---------------- fused main kernel (fp16 split-3, barrier-free mainloop) ----------------
// CTA = 32 rows (one b, 32 j's) x 512 cols, 256 threads, 8 column-warps.
// Each warp: disjoint 64-col slice, private B double buffer (cp.async + syncwarp).
__global__ __launch_bounds__(256, 2) void fused_kernel(
    const float* __restrict__ inputs,
    const float* __restrict__ state,
    const float* __restrict__ keys,
    float* __restrict__ out)
{
    extern __shared__ char smraw[];
    uint4* Bbuf  = reinterpret_cast<uint4*>(smraw);                 // 8 x [2][64][4] uint4 = 64KB
    float* gate  = reinterpret_cast<float*>(smraw + 65536);         // [32]
    float* normv = gate + 32;                                        // [32]
    float* red   = normv + 32;                                       // [8][32]

    int tid  = threadIdx.x;
    int bx   = blockIdx.x;
    int row0 = bx * 32;
    int b    = bx >> 1;
    int j0   = (bx & 1) * 32;

    int lane = tid & 31;
    int w    = tid >> 5;
    int gid  = lane >> 2;
    int tig  = lane & 3;
    int cb   = w * 64;

    uint4* mybuf = Bbuf + w * 512;                    // [2][64][4] uint4 (8KB)
    const uint4* usrc = g_UH + (size_t)cb * 128;      // col-major: col*128 + s*4 + tg

    // per-warp prefetch of slabs 0 and 1 (each 64 cols x 4 = 256 uint4 = 4KB)
#pragma unroll
    for (int st = 0; st < 2; st++) {
#pragma unroll
        for (int q = 0; q < 8; q++) {
            int idx = lane + 32 * q;                  // 0..255
            int col = idx >> 2, p = idx & 3;
            cp_async16(mybuf + st * 256 + idx, usrc + (size_t)col * 128 + st * 4 + p);
        }
        cp_commit();
    }

    // Gates: warp w -> rows 4w..4w+3 ; z = inputs[b].(s_row + key_j)
    {
        const float* ir = inputs + (size_t)b * Ddim;
#pragma unroll
        for (int i = 0; i < 4; i++) {
            int r = w * 4 + i;
            const float* sr = state + (size_t)(row0 + r) * Ddim;
            const float* kr = keys + (size_t)(j0 + r) * Ddim;
            float z = 0.f;
            for (int k = lane; k < Ddim; k += 32)
                z += ir[k] * (sr[k] + kr[k]);
#pragma unroll
            for (int o = 16; o; o >>= 1) z += __shfl_xor_sync(0xffffffffu, z, o);
            if (lane == 0) gate[r] = 1.f / (1.f + expf(-z));
        }
    }

    // -------- barrier-free fp16 split-3 mainloop: 32 k16-slabs --------
    float acc[2][8][4];
#pragma unroll
    for (int mi = 0; mi < 2; mi++)
#pragma unroll
        for (int nf = 0; nf < 8; nf++)
#pragma unroll
            for (int c = 0; c < 4; c++) acc[mi][nf][c] = 0.f;

    const uint2* Ar0a = g_A2h + (size_t)(row0 + gid) * 256;        // mi=0 rows
    const uint2* Ar8a = Ar0a + (size_t)8 * 256;
    const uint2* Ar0b = g_A2h + (size_t)(row0 + 16 + gid) * 256;   // mi=1 rows
    const uint2* Ar8b = Ar0b + (size_t)8 * 256;

#pragma unroll 1
    for (int s = 0; s < 32; s++) {
        if (s < 30) cp_wait1(); else cp_wait0();
        __syncwarp();
        int kb = s * 8;

        // A fragments (pre-split, no CVTs): 8 x LDG.64
        unsigned ah[2][4], al[2][4];
        {
            uint2 a0 = Ar0a[kb + tig];
            uint2 a1 = Ar8a[kb + tig];
            uint2 a2 = Ar0a[kb + tig + 4];
            uint2 a3 = Ar8a[kb + tig + 4];
            ah[0][0] = a0.x; ah[0][1] = a1.x; ah[0][2] = a2.x; ah[0][3] = a3.x;
            al[0][0] = a0.y; al[0][1] = a1.y; al[0][2] = a2.y; al[0][3] = a3.y;
        }
        {
            uint2 a0 = Ar0b[kb + tig];
            uint2 a1 = Ar8b[kb + tig];
            uint2 a2 = Ar0b[kb + tig + 4];
            uint2 a3 = Ar8b[kb + tig + 4];
            ah[1][0] = a0.x; ah[1][1] = a1.x; ah[1][2] = a2.x; ah[1][3] = a3.x;
            al[1][0] = a0.y; al[1][1] = a1.y; al[1][2] = a2.y; al[1][3] = a3.y;
        }

        const uint4* Bs = mybuf + (s & 1) * 256;
#pragma unroll
        for (int half = 0; half < 2; half++) {
            uint4 bq[4];
#pragma unroll
            for (int q = 0; q < 4; q++) {
                int nf = half * 4 + q;
                bq[q] = Bs[(nf * 8 + gid) * 4 + tig];
            }
            // hh
#pragma unroll
            for (int q = 0; q < 4; q++)
#pragma unroll
                for (int mi = 0; mi < 2; mi++)
                    mma_f16(acc[mi][half * 4 + q], ah[mi], bq[q].x, bq[q].y);
            // lh
#pragma unroll
            for (int q = 0; q < 4; q++)
#pragma unroll
                for (int mi = 0; mi < 2; mi++)
                    mma_f16(acc[mi][half * 4 + q], al[mi], bq[q].x, bq[q].y);
            // hl
#pragma unroll
            for (int q = 0; q < 4; q++)
#pragma unroll
                for (int mi = 0; mi < 2; mi++)
                    mma_f16(acc[mi][half * 4 + q], ah[mi], bq[q].z, bq[q].w);
        }

        if (s + 2 < 32) {
            uint4* Ud = mybuf + (s & 1) * 256;
#pragma unroll
            for (int q = 0; q < 8; q++) {
                int idx = lane + 32 * q;
                int col = idx >> 2, p = idx & 3;
                cp_async16(Ud + idx, usrc + (size_t)col * 128 + (s + 2) * 4 + p);
            }
            cp_commit();
        }
    }

    __syncthreads();   // gates visible

    // -------- epilogue: v = s + g*relu(acc + Q[b] + P[j]); row-norm partials --------
    const float* Qb = g_Q + (size_t)b * Ddim;
    float part[4];
#pragma unroll
    for (int mi = 0; mi < 2; mi++) {
#pragma unroll
        for (int h = 0; h < 2; h++) {
            int r = mi * 16 + h * 8 + gid;
            float g = gate[r];
            const float* Pr = g_P + (size_t)(j0 + r) * Ddim;
            const float* Sr = state + (size_t)(row0 + r) * Ddim;
            float psum = 0.f;
#pragma unroll
            for (int nf = 0; nf < 8; nf++) {
                int c0 = cb + nf * 8 + tig * 2;
                float2 p2 = *reinterpret_cast<const float2*>(Pr + c0);
                float2 q2 = *reinterpret_cast<const float2*>(Qb + c0);
                float2 s2 = *reinterpret_cast<const float2*>(Sr + c0);
                float pre0 = acc[mi][nf][h * 2 + 0] + q2.x + p2.x;
                float pre1 = acc[mi][nf][h * 2 + 1] + q2.y + p2.y;
                float v0 = s2.x + g * fmaxf(pre0, 0.f);
                float v1 = s2.y + g * fmaxf(pre1, 0.f);
                acc[mi][nf][h * 2 + 0] = v0;
                acc[mi][nf][h * 2 + 1] = v1;
                psum += v0 * v0 + v1 * v1;
            }
            part[mi * 2 + h] = psum;
        }
    }
#pragma unroll
    for (int i = 0; i < 4; i++) {
        part[i] += __shfl_xor_sync(0xffffffffu, part[i], 1);
        part[i] += __shfl_xor_sync(0xffffffffu, part[i], 2);
    }
    if (tig == 0) {
#pragma unroll
        for (int mi = 0; mi < 2; mi++)
#pragma unroll
            for (int h = 0; h < 2; h++)
                red[w * 32 + mi * 16 + h * 8 + gid] = part[mi * 2 + h];
    }
    __syncthreads();
    if (tid < 32) {
        float sum = 0.f;
#pragma unroll
        for (int ww = 0; ww < 8; ww++) sum += red[ww * 32 + tid];
        normv[tid] = fmaxf(sqrtf(sum), 1e-12f);
    }
    __syncthreads();

    // out = (v > 0) ? norm : v
#pragma unroll
    for (int mi = 0; mi < 2; mi++) {
#pragma unroll
        for (int h = 0; h < 2; h++) {
            int r = mi * 16 + h * 8 + gid;
            float n = normv[r];
            float* orow = out + (size_t)(row0 + r) * Ddim;
#pragma unroll
            for (int nf = 0; nf < 8; nf++) {
                int c0 = cb + nf * 8 + tig * 2;
                float v0 = acc[mi][nf][h * 2 + 0];
                float v1 = acc[mi][nf][h * 2 + 1];
                float2 o;
                o.x = v0 > 0.f ? n : v0;
                o.y = v1 > 0.f ? n : v1;
                *reinterpret_cast<float2*>(orow + c0) = o;
            }
        }
    }
}

extern "C" void kernel_launch(void* const* d_in, const int* in_sizes, int n_in,
                              void* d_out, int out_size)
{
    const float* inputs = (const float*)d_in[0];
    const float* state  = (const float*)d_in[1];
    const float* keys   = (const float*)d_in[2];
    const float* U      = (const float*)d_in[3];
    const float* V      = (const float*)d_in[4];
    const float* W      = (const float*)d_in[5];
    const float* Ubias  = (const float*)d_in[6];
    float* out = (float*)d_out;
    (void)in_sizes; (void)n_in; (void)out_size;

    // Q(32) + P(8) + UH(64) + A2h(2048) = 2152 blocks
    precompute_kernel<<<2152, 256>>>(inputs, keys, state, V, W, U, Ubias);

    size_t smem = 65536 + (32 + 32 + 8 * 32) * sizeof(float);
    cudaFuncSetAttribute(fused_kernel, cudaFuncAttributeMaxDynamicSharedMemorySize, (int)smem);
    fused_kernel<<<(Bdim * Jdim) / 32, 256, smem>>>(inputs, state, keys, out);
}